// round 16
// baseline (speedup 1.0000x reference)
#include <cuda_runtime.h>
#include <cuda_fp16.h>

#define NT 384

typedef unsigned long long ull;

// Scratch (allowed: __device__ globals, no runtime allocation)
// Conv1 weight image: [chunk8][cp25][h2][cil8][k9 pad->73], h stride 73 ull, cp stride 146,
// chunk stride 3650 ull. float2 = {w1[2cp][ci][k], w1[2cp+1][ci][k]}, ci = chunk*16+h*8+cil.
__device__ __align__(16) float2 g_w1s4[8 * 25 * 146];
__device__ __align__(16) float4 g_w2p[64 * 42];   // pconv weights: k padded 3->4
__device__ float2 g_Wt2[128 * 960];  // [(d*8+i)*960 + pair] = {W[p0][d][i], W[p0+1][d][i]}

#define W1S_N (8 * 25 * 146)
#define W2P_N (64 * 42)
#define WT2_N (128 * 960)

__device__ __forceinline__ ull pack2(float lo, float hi) {
    ull r; asm("mov.b64 %0, {%1, %2};" : "=l"(r) : "f"(lo), "f"(hi)); return r;
}
__device__ __forceinline__ void unpack2(ull v, float& lo, float& hi) {
    asm("mov.b64 {%0, %1}, %2;" : "=f"(lo), "=f"(hi) : "l"(v));
}
__device__ __forceinline__ void ffma2(ull& d, ull a, ull b) {
    asm("fma.rn.f32x2 %0, %1, %2, %0;" : "+l"(d) : "l"(a), "l"(b));
}

__global__ void prep_kernel(const float* __restrict__ w1, const float* __restrict__ w2,
                            const float* __restrict__ W) {
    int idx = blockIdx.x * blockDim.x + threadIdx.x;
    if (idx < W1S_N) {
        int chunk = idx / 3650;
        int r = idx - chunk * 3650;
        int cp = r / 146;
        int q = r - cp * 146;
        int h = q / 73;
        int w = q - h * 73;
        int cil = w / 9, k = w - cil * 9;
        float lo = 0.f, hi = 0.f;
        if (w < 72) {
            int ci = chunk * 16 + h * 8 + cil;
            lo = w1[((2 * cp) * 128 + ci) * 9 + k];
            hi = w1[((2 * cp + 1) * 128 + ci) * 9 + k];
        }
        g_w1s4[idx] = make_float2(lo, hi);
    } else if (idx < W1S_N + W2P_N) {
        int j = idx - W1S_N;
        const float* s = w2 + j * 3;
        g_w2p[j] = make_float4(s[0], s[1], s[2], 0.f);
    } else {
        int t = idx - (W1S_N + W2P_N);
        if (t < WT2_N) {
            int pair = t % 960;
            int di = t / 960;          // d*8 + i
            int p0 = 2 * pair;
            int o = p0 / 384, c0 = p0 % 384;
            float lo = W[(size_t)o * 49152 + c0 * 128 + di];
            float hi = W[(size_t)o * 49152 + (c0 + 1) * 128 + di];
            g_Wt2[t] = make_float2(lo, hi);
        }
    }
}

// Shared memory layout (floats) — heavy overlay; phases annotated
#define OFF_SP    0        // [4][80]: 320 (alloc 480)
#define OFF_S     480      // 80
#define OFF_V     560      // 80
#define OFF_SQ    640      // 8
// union region base 672:
#define OFF_XD    672      // phases 0-1: duplicated x {v,v} ull pairs, 13584 floats
#define OFF_WSTG  14256    // phases 0-1: conv1 weight chunk stage, 7300 (3650 ull)
#define OFF_H     21560    // phases 1-2: sH [42][52] = 2184 (16B-aligned rows)
#define OFF_PART  23744    // phase 1: ci-half partials, 2100
#define OFF_W2    672      // phase 2: pconv weights, 10752
#define OFF_P     11424    // phases 2-3: sP [64][49] = 3136
#define OFF_U     672      // phases 3-4: sU [384][8] = 3072
#define OFF_UH    3744     // phases 4-5: u_hat fp16, 15860 floats (31720 half)
#define OFF_B     672      // phase 5: sB [5][384] = 1920
#define OFF_C     19604    // phase 5: sC [5][384] = 1920
#define SMEM_FLTS 25844

#define UH_D_STRIDE 396    // halves per d row (384 + 12 pad): conflict-free
#define UH_O_STRIDE 6344   // halves per o (16*396 + 8)
#define W1_H_STRIDE  73    // ull
#define W1_CP_STRIDE 146   // ull
#define W1_CHUNK_U4  1825  // uint4 per 16-ci chunk

// sXD row addressing (ull): ci*53 + (ci>>4) pad
__device__ __forceinline__ int XDROW(int ci) { return ci * 53 + (ci >> 4); }

__global__ __launch_bounds__(NT, 2)
void caps_kernel(const float* __restrict__ x,
                 const float* __restrict__ b1,
                 const float* __restrict__ b2,
                 float* __restrict__ out)
{
    extern __shared__ float sm[];
    float* sSp   = sm + OFF_SP;
    float* sS    = sm + OFF_S;
    float* sV    = sm + OFF_V;
    float* sSq   = sm + OFF_SQ;
    float* sH    = sm + OFF_H;
    float* sP    = sm + OFF_P;
    float* sU    = sm + OFF_U;
    float* sB    = sm + OFF_B;
    float* sC    = sm + OFF_C;
    __half* uh   = (__half*)(sm + OFF_UH);
    ull* sXD     = (ull*)(sm + OFF_XD);

    const int tid = threadIdx.x;
    const int b   = blockIdx.x;

    // ---- Phase 0: load x[b] -> sXD as duplicated {v,v} pairs; prestage chunk 0 ----
    {
        const float* xg = x + (size_t)b * 6400;
        for (int i = tid; i < 6400; i += NT) {
            int pos = i >> 7, ci = i & 127;
            float v = xg[i];
            sXD[XDROW(ci) + pos] = pack2(v, v);
        }
        if (tid < 256) {
            int ci = tid >> 1;
            sXD[XDROW(ci) + 50 + (tid & 1)] = 0ULL;
        }
        const uint4* src = (const uint4*)g_w1s4;
        uint4* dst = (uint4*)(sm + OFF_WSTG);
        for (int i = tid; i < W1_CHUNK_U4; i += NT) dst[i] = src[i];
    }
    __syncthreads();

    // ---- Phase 1: conv1 + bias + relu -> sH[l][co] ----
    // 350 compute threads: cp(0..24) x lg(0..6, 6 l each) x h(8-ci half per chunk).
    {
        ull* sW = (ull*)(sm + OFF_WSTG);
        int cp = 0, h = 0, l0 = 0;
        float bb0 = 0.f, bb1 = 0.f;
        ull acc[6];
        #pragma unroll
        for (int j = 0; j < 6; ++j) acc[j] = pack2(0.f, 0.f);
        if (tid < 350) {
            cp = tid / 14;
            int r = tid - cp * 14;
            l0 = (r >> 1) * 6;
            h  = r & 1;
            bb0 = b1[2 * cp]; bb1 = b1[2 * cp + 1];
        }
        for (int chunk = 0; chunk < 8; ++chunk) {
            if (tid < 350) {
                const ull* wbase = sW + cp * W1_CP_STRIDE + h * W1_H_STRIDE;
                int cibase = chunk * 16 + h * 8;
                const ull* xp = sXD + XDROW(cibase) + l0;
                for (int cil = 0; cil < 8; ++cil, xp += 53) {
                    ull xd[14];
                    #pragma unroll
                    for (int m = 0; m < 14; ++m) xd[m] = xp[m];
                    const ull* wp = wbase + cil * 9;
                    ull wk[9];
                    #pragma unroll
                    for (int k = 0; k < 9; ++k) wk[k] = wp[k];
                    #pragma unroll
                    for (int k = 0; k < 9; ++k) {
                        #pragma unroll
                        for (int j = 0; j < 6; ++j)
                            ffma2(acc[j], wk[k], xd[k + j]);
                    }
                }
            }
            __syncthreads();
            if (chunk < 7) {
                const uint4* src = (const uint4*)g_w1s4 + (chunk + 1) * W1_CHUNK_U4;
                uint4* dst = (uint4*)sW;
                for (int i = tid; i < W1_CHUNK_U4; i += NT) dst[i] = src[i];
                __syncthreads();
            }
        }
        // reduce the two ci-halves: h=1 stores partials, h=0 combines
        float* sPart = sm + OFF_PART;
        if (tid < 350 && h == 1) {
            int pi = tid >> 1;
            #pragma unroll
            for (int j = 0; j < 6; ++j) {
                float a, c;
                unpack2(acc[j], a, c);
                sPart[pi * 12 + 2 * j]     = a;
                sPart[pi * 12 + 2 * j + 1] = c;
            }
        }
        __syncthreads();
        if (tid < 350 && h == 0) {
            int pi = tid >> 1;
            int co0 = cp << 1;
            #pragma unroll
            for (int j = 0; j < 6; ++j) {
                float a, c;
                unpack2(acc[j], a, c);
                a += sPart[pi * 12 + 2 * j];
                c += sPart[pi * 12 + 2 * j + 1];
                int l = l0 + j;
                sH[l * 52 + co0]     = fmaxf(a + bb0, 0.f);
                sH[l * 52 + co0 + 1] = fmaxf(c + bb1, 0.f);
            }
        }
    }
    __syncthreads();

    // ---- Phase 2: pconv -> sP[po][t] (48 t per po), weights staged at OFF_W2 ----
    {
        float4* sW2 = (float4*)(sm + OFF_W2);
        for (int i = tid; i < 2688; i += NT) sW2[i] = g_w2p[i];
        __syncthreads();
        {
            int po = tid / 6, tg = tid % 6;
            int t0 = tg * 8;
            float bias = b2[po];
            float acc[8] = {0.f, 0.f, 0.f, 0.f, 0.f, 0.f, 0.f, 0.f};
            const float4* w2r = (const float4*)(sm + OFF_W2) + po * 42;
            for (int a = 0; a < 42; ++a) {
                float4 w = w2r[a];
                const float4* hr = (const float4*)(sH + a * 52 + t0);
                float4 v0 = hr[0], v1 = hr[1], v2 = hr[2];
                float xv[10] = {v0.x, v0.y, v0.z, v0.w, v1.x, v1.y, v1.z, v1.w, v2.x, v2.y};
                #pragma unroll
                for (int j = 0; j < 8; ++j)
                    acc[j] += w.x * xv[j] + w.y * xv[j + 1] + w.z * xv[j + 2];
            }
            #pragma unroll
            for (int j = 0; j < 8; ++j) sP[po * 49 + t0 + j] = acc[j] + bias;
        }
    }
    __syncthreads();

    // ---- Phase 3: primary-caps squash -> sU[c][i] ----
    {
        int po = tid / 6, g = tid % 6;
        const float* pr = sP + po * 49 + g * 8;
        float q[8];
        float sq = 0.f;
        #pragma unroll
        for (int i = 0; i < 8; ++i) { q[i] = pr[i]; sq += q[i] * q[i]; }
        float scale = (sq / (1.f + sq)) / (sqrtf(sq) + 1e-8f);
        #pragma unroll
        for (int i = 0; i < 8; ++i) sU[tid * 8 + i] = q[i] * scale;
    }
    __syncthreads();

    // ---- Phase 4: u_hat (fp16, d-major) via transposed W; 2 capsules per job ----
    {
        const ull* Wt = (const ull*)g_Wt2;
        __half2* uh2 = (__half2*)uh;
        for (int pair = tid; pair < 960; pair += NT) {
            int o = pair / 192;
            int cpi = pair - o * 192;      // capsule-pair index, c0 = 2*cpi
            int c0 = 2 * cpi;
            const float4* ua = (const float4*)(sU + c0 * 8);
            float4 A0 = ua[0], A1 = ua[1];   // u[c0]
            float4 B0 = ua[2], B1 = ua[3];   // u[c0+1]
            ull uu[8];
            uu[0] = pack2(A0.x, B0.x); uu[1] = pack2(A0.y, B0.y);
            uu[2] = pack2(A0.z, B0.z); uu[3] = pack2(A0.w, B0.w);
            uu[4] = pack2(A1.x, B1.x); uu[5] = pack2(A1.y, B1.y);
            uu[6] = pack2(A1.z, B1.z); uu[7] = pack2(A1.w, B1.w);
            const ull* wp = Wt + pair;
            __half2* dst = uh2 + o * (UH_O_STRIDE / 2) + cpi;
            #pragma unroll
            for (int d = 0; d < 16; ++d) {
                ull acc = pack2(0.f, 0.f);
                #pragma unroll
                for (int i = 0; i < 8; ++i)
                    ffma2(acc, wp[(d * 8 + i) * 960], uu[i]);
                float r0, r1;
                unpack2(acc, r0, r1);
                dst[d * (UH_D_STRIDE / 2)] = __floats2half2_rn(r0, r1);
            }
        }
    }
    __syncthreads();

    // ---- Phase 5: dynamic routing (3 iterations) ----
    // it=0: b==0 -> c = 0.2 exactly (skip softmax; write b, don't accumulate).
    for (int it = 0; it < 3; ++it) {
        if (it > 0) {
            float bb[5], m = -1e30f;
            #pragma unroll
            for (int o = 0; o < 5; ++o) { bb[o] = sB[o * 384 + tid]; m = fmaxf(m, bb[o]); }
            float e[5], ssum = 0.f;
            #pragma unroll
            for (int o = 0; o < 5; ++o) { e[o] = expf(bb[o] - m); ssum += e[o]; }
            float inv = 1.f / ssum;
            #pragma unroll
            for (int o = 0; o < 5; ++o) sC[o * 384 + tid] = e[o] * inv;
            __syncthreads();
        }
        // s[o][d] = sum_c c[o][c] * u_hat[o][c][d]  (4-way split over c, 96 each)
        if (tid < 320) {
            int ch = tid / 80, od = tid - ch * 80;
            int o = od >> 4, d = od & 15;
            int c0 = ch * 96;
            const uint2* u2 = (const uint2*)(uh + o * UH_O_STRIDE + d * UH_D_STRIDE + c0);
            float a0 = 0.f, a1 = 0.f, a2 = 0.f, a3 = 0.f;
            if (it == 0) {
                #pragma unroll 6
                for (int q = 0; q < 24; ++q) {
                    uint2 v = u2[q];
                    float2 f0 = __half22float2(*(const __half2*)&v.x);
                    float2 f1 = __half22float2(*(const __half2*)&v.y);
                    a0 += f0.x; a1 += f0.y; a2 += f1.x; a3 += f1.y;
                }
                sSp[ch * 80 + od] = 0.2f * ((a0 + a1) + (a2 + a3));
            } else {
                const float4* cc = (const float4*)(sC + o * 384 + c0);
                #pragma unroll 6
                for (int q = 0; q < 24; ++q) {
                    uint2 v = u2[q];
                    float2 f0 = __half22float2(*(const __half2*)&v.x);
                    float2 f1 = __half22float2(*(const __half2*)&v.y);
                    float4 cv = cc[q];
                    a0 += cv.x * f0.x; a1 += cv.y * f0.y;
                    a2 += cv.z * f1.x; a3 += cv.w * f1.y;
                }
                sSp[ch * 80 + od] = (a0 + a1) + (a2 + a3);
            }
        }
        __syncthreads();
        if (tid < 80) {
            float s = sSp[tid] + sSp[80 + tid] + sSp[160 + tid] + sSp[240 + tid];
            sS[tid] = s;
        }
        __syncthreads();
        if (tid < 5) {
            float sq = 0.f;
            #pragma unroll
            for (int d = 0; d < 16; ++d) { float v = sS[tid * 16 + d]; sq += v * v; }
            sSq[tid] = sq;
        }
        __syncthreads();
        if (tid < 80) {
            int o = tid >> 4;
            float sq = sSq[o];
            float v = sS[tid] * (sq / (1.f + sq)) / (sqrtf(sq) + 1e-8f);
            sV[tid] = v;
            if (it == 2) out[(size_t)b * 80 + tid] = v;
        }
        __syncthreads();
        if (it < 2) {
            // b[o][c] (+)= sum_d u_hat[o][c][d] * v[o][d]  (5 rows per thread)
            for (int p = tid; p < 1920; p += NT) {
                int o = p / 384;
                int c = p - o * 384;
                const __half* up = uh + o * UH_O_STRIDE + c;
                const float* vv = sV + o * 16;
                float acc = 0.f;
                #pragma unroll
                for (int d = 0; d < 16; ++d)
                    acc += __half2float(up[d * UH_D_STRIDE]) * vv[d];
                if (it == 0) sB[p] = acc;
                else         sB[p] += acc;
            }
            __syncthreads();
        }
    }
}

extern "C" void kernel_launch(void* const* d_in, const int* in_sizes, int n_in,
                              void* d_out, int out_size) {
    const float* x  = (const float*)d_in[0];
    const float* w1 = (const float*)d_in[1];
    const float* b1 = (const float*)d_in[2];
    const float* w2 = (const float*)d_in[3];
    const float* b2 = (const float*)d_in[4];
    const float* W  = (const float*)d_in[5];
    float* out = (float*)d_out;

    int B = in_sizes[0] / 6400;

    size_t smem_bytes = SMEM_FLTS * sizeof(float);
    cudaFuncSetAttribute(caps_kernel, cudaFuncAttributeMaxDynamicSharedMemorySize,
                         (int)smem_bytes);

    int prep_n = W1S_N + W2P_N + WT2_N;
    prep_kernel<<<(prep_n + 255) / 256, 256>>>(w1, w2, W);
    caps_kernel<<<B, NT, smem_bytes>>>(x, b1, b2, out);
}

// round 17
// speedup vs baseline: 1.2631x; 1.2631x over previous
#include <cuda_runtime.h>
#include <cuda_fp16.h>

#define NT 384

typedef unsigned long long ull;

// Scratch (allowed: __device__ globals, no runtime allocation)
// Conv1 weight image: [chunk8][cp25][h2][cil8][k9 pad->73], h stride 73 ull, cp stride 146,
// chunk stride 3650 ull. float2 = {w1[2cp][ci][k], w1[2cp+1][ci][k]}, ci = chunk*16+h*8+cil.
__device__ __align__(16) float2 g_w1s4[8 * 25 * 146];
__device__ __align__(16) float4 g_w2p[64 * 42];   // pconv weights: k padded 3->4
__device__ float2 g_Wt2[128 * 960];  // [(d*8+i)*960 + pair] = {W[p0][d][i], W[p0+1][d][i]}

#define W1S_N (8 * 25 * 146)
#define W2P_N (64 * 42)
#define WT2_N (128 * 960)

__device__ __forceinline__ ull pack2(float lo, float hi) {
    ull r; asm("mov.b64 %0, {%1, %2};" : "=l"(r) : "f"(lo), "f"(hi)); return r;
}
__device__ __forceinline__ void unpack2(ull v, float& lo, float& hi) {
    asm("mov.b64 {%0, %1}, %2;" : "=f"(lo), "=f"(hi) : "l"(v));
}
__device__ __forceinline__ void ffma2(ull& d, ull a, ull b) {
    asm("fma.rn.f32x2 %0, %1, %2, %0;" : "+l"(d) : "l"(a), "l"(b));
}

__global__ void prep_kernel(const float* __restrict__ w1, const float* __restrict__ w2,
                            const float* __restrict__ W) {
    int idx = blockIdx.x * blockDim.x + threadIdx.x;
    if (idx < W1S_N) {
        int chunk = idx / 3650;
        int r = idx - chunk * 3650;
        int cp = r / 146;
        int q = r - cp * 146;
        int h = q / 73;
        int w = q - h * 73;
        int cil = w / 9, k = w - cil * 9;
        float lo = 0.f, hi = 0.f;
        if (w < 72) {
            int ci = chunk * 16 + h * 8 + cil;
            lo = w1[((2 * cp) * 128 + ci) * 9 + k];
            hi = w1[((2 * cp + 1) * 128 + ci) * 9 + k];
        }
        g_w1s4[idx] = make_float2(lo, hi);
    } else if (idx < W1S_N + W2P_N) {
        int j = idx - W1S_N;
        const float* s = w2 + j * 3;
        g_w2p[j] = make_float4(s[0], s[1], s[2], 0.f);
    } else {
        int t = idx - (W1S_N + W2P_N);
        if (t < WT2_N) {
            int pair = t % 960;
            int di = t / 960;          // d*8 + i
            int p0 = 2 * pair;
            int o = p0 / 384, c0 = p0 % 384;
            float lo = W[(size_t)o * 49152 + c0 * 128 + di];
            float hi = W[(size_t)o * 49152 + (c0 + 1) * 128 + di];
            g_Wt2[t] = make_float2(lo, hi);
        }
    }
}

// x row addressing: 52 words/row + 4-word pad per 8-ci group (de-aliases h-halves)
__device__ __forceinline__ int XROW(int ci) { return ci * 52 + ((ci >> 3) << 2); }

// Shared memory layout (floats) — heavy overlay; phases annotated
#define OFF_SP    0        // [4][80]: 320 (alloc 480)
#define OFF_S     480      // 80
#define OFF_V     560      // 80
#define OFF_SQ    640      // 8
// union region base 672:
#define OFF_XT    672      // phases 0-1: x, 6720
#define OFF_WSTG  7392     // phases 0-1: conv1 weight chunk stage, 7300 (3650 ull)
#define OFF_H     14692    // phases 1-2: sH [42][52] = 2184
#define OFF_PART  17600    // phase 1: ci-half partials, 2100
#define OFF_W2    672      // phase 2: pconv weights, 10752
#define OFF_UH    3744     // phases 4-5: u_hat fp16, 15860 floats (31720 half)
#define OFF_B     672      // phase 5: sB [5][384] = 1920
#define OFF_C     19604    // phase 5: sC [5][384] = 1920
#define OFF_U     21524    // phases 2-4: sU [384][8] = 3072 (dedicated, no overlay)
#define SMEM_FLTS 24596

#define UH_D_STRIDE 396    // halves per d row (384 + 12 pad): conflict-free
#define UH_O_STRIDE 6344   // halves per o (16*396 + 8)
#define W1_H_STRIDE  73    // ull
#define W1_CP_STRIDE 146   // ull
#define W1_CHUNK_U4  1825  // uint4 per 16-ci chunk

__global__ __launch_bounds__(NT, 2)
void caps_kernel(const float* __restrict__ x,
                 const float* __restrict__ b1,
                 const float* __restrict__ b2,
                 float* __restrict__ out)
{
    extern __shared__ float sm[];
    float* sSp   = sm + OFF_SP;
    float* sS    = sm + OFF_S;
    float* sV    = sm + OFF_V;
    float* sSq   = sm + OFF_SQ;
    float* sXT   = sm + OFF_XT;
    float* sH    = sm + OFF_H;
    float* sU    = sm + OFF_U;
    float* sB    = sm + OFF_B;
    float* sC    = sm + OFF_C;
    __half* uh   = (__half*)(sm + OFF_UH);

    const int tid = threadIdx.x;
    const int b   = blockIdx.x;

    // ---- Phase 0: load x[b] -> sXT; prestage conv1 chunk 0 ----
    {
        const float* xg = x + (size_t)b * 6400;
        for (int i = tid; i < 6400; i += NT) {
            int pos = i >> 7, ci = i & 127;
            sXT[XROW(ci) + pos] = xg[i];
        }
        const uint4* src = (const uint4*)g_w1s4;
        uint4* dst = (uint4*)(sm + OFF_WSTG);
        for (int i = tid; i < W1_CHUNK_U4; i += NT) dst[i] = src[i];
    }
    __syncthreads();

    // ---- Phase 1: conv1 + bias + relu -> sH[l][co] ----
    // 350 compute threads: cp(0..24) x lg(0..6, 6 l each) x h(8-ci half per chunk).
    {
        ull* sW = (ull*)(sm + OFF_WSTG);
        int cp = 0, h = 0, l0 = 0;
        float bb0 = 0.f, bb1 = 0.f;
        ull acc[6];
        #pragma unroll
        for (int j = 0; j < 6; ++j) acc[j] = pack2(0.f, 0.f);
        if (tid < 350) {
            cp = tid / 14;
            int r = tid - cp * 14;
            l0 = (r >> 1) * 6;
            h  = r & 1;
            bb0 = b1[2 * cp]; bb1 = b1[2 * cp + 1];
        }
        for (int chunk = 0; chunk < 8; ++chunk) {
            if (tid < 350) {
                const ull* wbase = sW + cp * W1_CP_STRIDE + h * W1_H_STRIDE;
                int cibase = chunk * 16 + h * 8;
                for (int cil = 0; cil < 8; ++cil) {
                    int ci = cibase + cil;
                    const float2* xr = (const float2*)(sXT + XROW(ci) + l0);
                    float2 x0 = xr[0], x1 = xr[1], x2 = xr[2], x3 = xr[3];
                    float2 x4 = xr[4], x5 = xr[5], x6 = xr[6];
                    ull xd[14];
                    xd[0]  = pack2(x0.x, x0.x); xd[1]  = pack2(x0.y, x0.y);
                    xd[2]  = pack2(x1.x, x1.x); xd[3]  = pack2(x1.y, x1.y);
                    xd[4]  = pack2(x2.x, x2.x); xd[5]  = pack2(x2.y, x2.y);
                    xd[6]  = pack2(x3.x, x3.x); xd[7]  = pack2(x3.y, x3.y);
                    xd[8]  = pack2(x4.x, x4.x); xd[9]  = pack2(x4.y, x4.y);
                    xd[10] = pack2(x5.x, x5.x); xd[11] = pack2(x5.y, x5.y);
                    xd[12] = pack2(x6.x, x6.x); xd[13] = pack2(x6.y, x6.y);
                    const ull* wp = wbase + cil * 9;
                    ull wk[9];
                    #pragma unroll
                    for (int k = 0; k < 9; ++k) wk[k] = wp[k];
                    #pragma unroll
                    for (int k = 0; k < 9; ++k) {
                        #pragma unroll
                        for (int j = 0; j < 6; ++j)
                            ffma2(acc[j], wk[k], xd[k + j]);
                    }
                }
            }
            __syncthreads();
            if (chunk < 7) {
                const uint4* src = (const uint4*)g_w1s4 + (chunk + 1) * W1_CHUNK_U4;
                uint4* dst = (uint4*)sW;
                for (int i = tid; i < W1_CHUNK_U4; i += NT) dst[i] = src[i];
                __syncthreads();
            }
        }
        // reduce the two ci-halves: h=1 stores partials, h=0 combines
        float* sPart = sm + OFF_PART;
        if (tid < 350 && h == 1) {
            int pi = tid >> 1;
            #pragma unroll
            for (int j = 0; j < 6; ++j) {
                float a, c;
                unpack2(acc[j], a, c);
                sPart[pi * 12 + 2 * j]     = a;
                sPart[pi * 12 + 2 * j + 1] = c;
            }
        }
        __syncthreads();
        if (tid < 350 && h == 0) {
            int pi = tid >> 1;
            int co0 = cp << 1;
            #pragma unroll
            for (int j = 0; j < 6; ++j) {
                float a, c;
                unpack2(acc[j], a, c);
                a += sPart[pi * 12 + 2 * j];
                c += sPart[pi * 12 + 2 * j + 1];
                int l = l0 + j;
                sH[l * 52 + co0]     = fmaxf(a + bb0, 0.f);
                sH[l * 52 + co0 + 1] = fmaxf(c + bb1, 0.f);
            }
        }
    }
    __syncthreads();

    // ---- Phase 2+3 fused: pconv + squash -> sU[c][i] ----
    // Thread (po, tg) computes t = 8tg..8tg+7 == capsule c = po*6+tg, i = 0..7.
    {
        float4* sW2 = (float4*)(sm + OFF_W2);
        for (int i = tid; i < 2688; i += NT) sW2[i] = g_w2p[i];
        __syncthreads();
        {
            int po = tid / 6, tg = tid % 6;
            int t0 = tg * 8;
            float bias = b2[po];
            float acc[8] = {0.f, 0.f, 0.f, 0.f, 0.f, 0.f, 0.f, 0.f};
            const float4* w2r = (const float4*)(sm + OFF_W2) + po * 42;
            for (int a = 0; a < 42; ++a) {
                float4 w = w2r[a];
                const float4* hr = (const float4*)(sH + a * 52 + t0);
                float4 v0 = hr[0], v1 = hr[1], v2 = hr[2];
                float xv[10] = {v0.x, v0.y, v0.z, v0.w, v1.x, v1.y, v1.z, v1.w, v2.x, v2.y};
                #pragma unroll
                for (int j = 0; j < 8; ++j)
                    acc[j] += w.x * xv[j] + w.y * xv[j + 1] + w.z * xv[j + 2];
            }
            float sq = 0.f;
            #pragma unroll
            for (int j = 0; j < 8; ++j) { acc[j] += bias; sq += acc[j] * acc[j]; }
            float scale = (sq / (1.f + sq)) / (sqrtf(sq) + 1e-8f);
            int c = po * 6 + tg;
            #pragma unroll
            for (int j = 0; j < 8; ++j) sU[c * 8 + j] = acc[j] * scale;
        }
    }
    __syncthreads();

    // ---- Phase 4: u_hat (fp16, d-major) via transposed W; 2 capsules per job ----
    {
        const ull* Wt = (const ull*)g_Wt2;
        __half2* uh2 = (__half2*)uh;
        for (int pair = tid; pair < 960; pair += NT) {
            int o = pair / 192;
            int cpi = pair - o * 192;      // capsule-pair index, c0 = 2*cpi
            int c0 = 2 * cpi;
            const float4* ua = (const float4*)(sU + c0 * 8);
            float4 A0 = ua[0], A1 = ua[1];   // u[c0]
            float4 B0 = ua[2], B1 = ua[3];   // u[c0+1]
            ull uu[8];
            uu[0] = pack2(A0.x, B0.x); uu[1] = pack2(A0.y, B0.y);
            uu[2] = pack2(A0.z, B0.z); uu[3] = pack2(A0.w, B0.w);
            uu[4] = pack2(A1.x, B1.x); uu[5] = pack2(A1.y, B1.y);
            uu[6] = pack2(A1.z, B1.z); uu[7] = pack2(A1.w, B1.w);
            const ull* wp = Wt + pair;
            __half2* dst = uh2 + o * (UH_O_STRIDE / 2) + cpi;
            #pragma unroll
            for (int d = 0; d < 16; ++d) {
                ull acc = pack2(0.f, 0.f);
                #pragma unroll
                for (int i = 0; i < 8; ++i)
                    ffma2(acc, wp[(d * 8 + i) * 960], uu[i]);
                float r0, r1;
                unpack2(acc, r0, r1);
                dst[d * (UH_D_STRIDE / 2)] = __floats2half2_rn(r0, r1);
            }
        }
    }
    __syncthreads();

    // ---- Phase 5: dynamic routing (3 iterations) ----
    // it=0: b==0 -> c = 0.2 exactly (skip softmax; write b, don't accumulate).
    for (int it = 0; it < 3; ++it) {
        if (it > 0) {
            float bb[5], m = -1e30f;
            #pragma unroll
            for (int o = 0; o < 5; ++o) { bb[o] = sB[o * 384 + tid]; m = fmaxf(m, bb[o]); }
            float e[5], ssum = 0.f;
            #pragma unroll
            for (int o = 0; o < 5; ++o) { e[o] = expf(bb[o] - m); ssum += e[o]; }
            float inv = 1.f / ssum;
            #pragma unroll
            for (int o = 0; o < 5; ++o) sC[o * 384 + tid] = e[o] * inv;
            __syncthreads();
        }
        // s[o][d] = sum_c c[o][c] * u_hat[o][c][d]  (4-way split over c, 96 each)
        if (tid < 320) {
            int ch = tid / 80, od = tid - ch * 80;
            int o = od >> 4, d = od & 15;
            int c0 = ch * 96;
            const uint2* u2 = (const uint2*)(uh + o * UH_O_STRIDE + d * UH_D_STRIDE + c0);
            float a0 = 0.f, a1 = 0.f, a2 = 0.f, a3 = 0.f;
            if (it == 0) {
                #pragma unroll 6
                for (int q = 0; q < 24; ++q) {
                    uint2 v = u2[q];
                    float2 f0 = __half22float2(*(const __half2*)&v.x);
                    float2 f1 = __half22float2(*(const __half2*)&v.y);
                    a0 += f0.x; a1 += f0.y; a2 += f1.x; a3 += f1.y;
                }
                sSp[ch * 80 + od] = 0.2f * ((a0 + a1) + (a2 + a3));
            } else {
                const float4* cc = (const float4*)(sC + o * 384 + c0);
                #pragma unroll 6
                for (int q = 0; q < 24; ++q) {
                    uint2 v = u2[q];
                    float2 f0 = __half22float2(*(const __half2*)&v.x);
                    float2 f1 = __half22float2(*(const __half2*)&v.y);
                    float4 cv = cc[q];
                    a0 += cv.x * f0.x; a1 += cv.y * f0.y;
                    a2 += cv.z * f1.x; a3 += cv.w * f1.y;
                }
                sSp[ch * 80 + od] = (a0 + a1) + (a2 + a3);
            }
        }
        __syncthreads();
        if (tid < 80) {
            float s = sSp[tid] + sSp[80 + tid] + sSp[160 + tid] + sSp[240 + tid];
            sS[tid] = s;
        }
        __syncthreads();
        if (tid < 5) {
            float sq = 0.f;
            #pragma unroll
            for (int d = 0; d < 16; ++d) { float v = sS[tid * 16 + d]; sq += v * v; }
            sSq[tid] = sq;
        }
        __syncthreads();
        if (tid < 80) {
            int o = tid >> 4;
            float sq = sSq[o];
            float v = sS[tid] * (sq / (1.f + sq)) / (sqrtf(sq) + 1e-8f);
            sV[tid] = v;
            if (it == 2) out[(size_t)b * 80 + tid] = v;
        }
        __syncthreads();
        if (it < 2) {
            // b[o][c0..c0+1] (+)= sum_d u_hat[o][c][d] * v[o][d]  (half2 pairs)
            const __half2* uh2 = (const __half2*)uh;
            for (int j = tid; j < 960; j += NT) {
                int o = j / 192;
                int cpi = j - o * 192;
                const __half2* up = uh2 + o * (UH_O_STRIDE / 2) + cpi;
                const float* vv = sV + o * 16;
                float a0 = 0.f, a1 = 0.f;
                #pragma unroll
                for (int d = 0; d < 16; ++d) {
                    float2 f = __half22float2(up[d * (UH_D_STRIDE / 2)]);
                    a0 += f.x * vv[d];
                    a1 += f.y * vv[d];
                }
                int p = o * 384 + 2 * cpi;
                if (it == 0) { sB[p] = a0;  sB[p + 1] = a1; }
                else         { sB[p] += a0; sB[p + 1] += a1; }
            }
            __syncthreads();
        }
    }
}

extern "C" void kernel_launch(void* const* d_in, const int* in_sizes, int n_in,
                              void* d_out, int out_size) {
    const float* x  = (const float*)d_in[0];
    const float* w1 = (const float*)d_in[1];
    const float* b1 = (const float*)d_in[2];
    const float* w2 = (const float*)d_in[3];
    const float* b2 = (const float*)d_in[4];
    const float* W  = (const float*)d_in[5];
    float* out = (float*)d_out;

    int B = in_sizes[0] / 6400;

    size_t smem_bytes = SMEM_FLTS * sizeof(float);
    cudaFuncSetAttribute(caps_kernel, cudaFuncAttributeMaxDynamicSharedMemorySize,
                         (int)smem_bytes);

    int prep_n = W1S_N + W2P_N + WT2_N;
    prep_kernel<<<(prep_n + 255) / 256, 256>>>(w1, w2, W);
    caps_kernel<<<B, NT, smem_bytes>>>(x, b1, b2, out);
}